// round 2
// baseline (speedup 1.0000x reference)
#include <cuda_runtime.h>

#define V_N   100000
#define E_N   1600000
#define NI    128
#define HDIM  50
#define HP    25          // HDIM/2 packed f32x2 pairs
#define PADW  52          // padded scratch row (13 float4)
#define EB    512         // edges per tile
#define NT    256

typedef unsigned long long u64;

__device__ float g_left [(size_t)V_N * PADW];
__device__ float g_right[(size_t)V_N * PADW];
__device__ float g_acc  [(size_t)V_N * PADW];

// ---- helpers --------------------------------------------------------------
__device__ __forceinline__ u64 pk2(float x, float y) {
    u64 r; asm("mov.b64 %0, {%1, %2};" : "=l"(r) : "f"(x), "f"(y)); return r;
}
__device__ __forceinline__ float2 up2(u64 v) {
    float2 r; asm("mov.b64 {%0, %1}, %2;" : "=f"(r.x), "=f"(r.y) : "l"(v)); return r;
}
__device__ __forceinline__ u64 ffma2(u64 a, u64 b, u64 c) {
    u64 d; asm("fma.rn.f32x2 %0, %1, %2, %3;" : "=l"(d) : "l"(a), "l"(b), "l"(c)); return d;
}
__device__ __forceinline__ float relu_f(float x) { return fmaxf(x, 0.0f); }

__device__ __forceinline__ void red4(float* p, float a, float b, float c, float d) {
    asm volatile("red.global.add.v4.f32 [%0], {%1,%2,%3,%4};"
                 :: "l"(p), "f"(a), "f"(b), "f"(c), "f"(d) : "memory");
}
__device__ __forceinline__ void red2(float* p, float a, float b) {
    asm volatile("red.global.add.v2.f32 [%0], {%1,%2};"
                 :: "l"(p), "f"(a), "f"(b) : "memory");
}

// acc{0,1}[jj] += x{0,1} * Wrow[2jj..2jj+1]  (two independent rows share W)
template <int W2>
__device__ __forceinline__ void accum_row(u64* a0, u64* a1, float x0, float x1,
                                          const float* Wrow) {
    u64 e0 = pk2(x0, x0), e1 = pk2(x1, x1);
    const u64* w = reinterpret_cast<const u64*>(Wrow);
    #pragma unroll
    for (int jj = 0; jj < W2; jj++) {
        a0[jj] = ffma2(e0, w[jj], a0[jj]);
        a1[jj] = ffma2(e1, w[jj], a1[jj]);
    }
}

// ---------------------------------------------------------------------------
// Kernel 1: left/right tables (no relu) + zero scatter accumulator
// ---------------------------------------------------------------------------
__global__ void __launch_bounds__(NT) k_node_lr(
    const float* __restrict__ nf,
    const float* __restrict__ w_l, const float* __restrict__ b_l,
    const float* __restrict__ w_r, const float* __restrict__ b_r)
{
    extern __shared__ float sm[];
    float* s_wl = sm;
    float* s_wr = sm + NI * HDIM;
    float* s_bl = s_wr + NI * HDIM;
    float* s_br = s_bl + HDIM;
    for (int i = threadIdx.x; i < NI * HDIM; i += NT) { s_wl[i] = w_l[i]; s_wr[i] = w_r[i]; }
    if (threadIdx.x < HDIM) { s_bl[threadIdx.x] = b_l[threadIdx.x]; s_br[threadIdx.x] = b_r[threadIdx.x]; }

    {   // zero g_acc
        float4 z = make_float4(0.f, 0.f, 0.f, 0.f);
        size_t tot = (size_t)V_N * PADW / 4;
        for (size_t i = (size_t)blockIdx.x * NT + threadIdx.x; i < tot; i += (size_t)gridDim.x * NT)
            reinterpret_cast<float4*>(g_acc)[i] = z;
    }
    __syncthreads();

    int v0 = (blockIdx.x * NT + threadIdx.x) * 2;
    if (v0 >= V_N) return;
    int v1 = v0 + 1;
    const float4* r0 = reinterpret_cast<const float4*>(nf + (size_t)v0 * NI);
    const float4* r1 = reinterpret_cast<const float4*>(nf + (size_t)v1 * NI);

    #pragma unroll 1
    for (int pass = 0; pass < 2; pass++) {
        const float* W = pass ? s_wr : s_wl;
        const u64*  B2 = reinterpret_cast<const u64*>(pass ? s_br : s_bl);
        u64 a0[HP], a1[HP];
        #pragma unroll
        for (int jj = 0; jj < HP; jj++) { a0[jj] = B2[jj]; a1[jj] = B2[jj]; }
        #pragma unroll 1
        for (int c = 0; c < NI / 4; c++) {
            float4 x0 = __ldg(r0 + c), x1 = __ldg(r1 + c);
            accum_row<HP>(a0, a1, x0.x, x1.x, W + (4 * c + 0) * HDIM);
            accum_row<HP>(a0, a1, x0.y, x1.y, W + (4 * c + 1) * HDIM);
            accum_row<HP>(a0, a1, x0.z, x1.z, W + (4 * c + 2) * HDIM);
            accum_row<HP>(a0, a1, x0.w, x1.w, W + (4 * c + 3) * HDIM);
        }
        float* dp = pass ? g_right : g_left;
        float* o0 = dp + (size_t)v0 * PADW;
        float* o1 = dp + (size_t)v1 * PADW;
        #pragma unroll
        for (int jj = 0; jj < HP; jj++) {
            reinterpret_cast<float2*>(o0)[jj] = up2(a0[jj]);
            reinterpret_cast<float2*>(o1)[jj] = up2(a1[jj]);
        }
        o0[50] = 0.f; o0[51] = 0.f; o1[50] = 0.f; o1[51] = 0.f;
    }
}

// out += relu(a[gathered] + b[gathered]) @ W[0:50] for two edges
__device__ __forceinline__ void gather_fold(u64* o0, u64* o1,
    const float4* a0p, const float4* b0p, const float4* a1p, const float4* b1p,
    const float* Wbase)
{
    #pragma unroll 1
    for (int c = 0; c < 12; c++) {
        float4 a0 = __ldg(a0p + c), b0 = __ldg(b0p + c);
        float4 a1 = __ldg(a1p + c), b1 = __ldg(b1p + c);
        const float* W = Wbase + 4 * c * HDIM;
        accum_row<HP>(o0, o1, relu_f(a0.x + b0.x), relu_f(a1.x + b1.x), W);
        accum_row<HP>(o0, o1, relu_f(a0.y + b0.y), relu_f(a1.y + b1.y), W + HDIM);
        accum_row<HP>(o0, o1, relu_f(a0.z + b0.z), relu_f(a1.z + b1.z), W + 2 * HDIM);
        accum_row<HP>(o0, o1, relu_f(a0.w + b0.w), relu_f(a1.w + b1.w), W + 3 * HDIM);
    }
    float4 a0 = __ldg(a0p + 12), b0 = __ldg(b0p + 12);
    float4 a1 = __ldg(a1p + 12), b1 = __ldg(b1p + 12);
    const float* W = Wbase + 48 * HDIM;
    accum_row<HP>(o0, o1, relu_f(a0.x + b0.x), relu_f(a1.x + b1.x), W);
    accum_row<HP>(o0, o1, relu_f(a0.y + b0.y), relu_f(a1.y + b1.y), W + HDIM);
}

// ---------------------------------------------------------------------------
// Kernel 2: edge pass (persistent, weights loaded once per SM)
// ---------------------------------------------------------------------------
__global__ void __launch_bounds__(NT) k_edge(
    const float* __restrict__ ef, const int* __restrict__ srcp, const int* __restrict__ dstp,
    const float* __restrict__ w_e2n, const float* __restrict__ b_e2n,
    const float* __restrict__ w_e2e, const float* __restrict__ b_e2e,
    const float* __restrict__ w_u,  const float* __restrict__ b_u,
    float* __restrict__ out_edge)
{
    extern __shared__ float sm[];
    float* s_ef  = sm;                       // EB*51
    float* s_w2n = s_ef + EB * 51;           // 2500
    float* s_w2e = s_w2n + 2500;             // 2500
    float* s_wu  = s_w2e + 2500;             // 7500
    float* s_b2n = s_wu + 7500;
    float* s_b2e = s_b2n + HDIM;
    float* s_bu  = s_b2e + HDIM;
    int*   s_src = reinterpret_cast<int*>(s_bu + HDIM);
    int*   s_dst = s_src + EB;

    for (int i = threadIdx.x; i < 2500; i += NT) { s_w2n[i] = w_e2n[i]; s_w2e[i] = w_e2e[i]; }
    for (int i = threadIdx.x; i < 7500; i += NT) s_wu[i] = w_u[i];
    if (threadIdx.x < HDIM) {
        s_b2n[threadIdx.x] = b_e2n[threadIdx.x];
        s_b2e[threadIdx.x] = b_e2e[threadIdx.x];
        s_bu [threadIdx.x] = b_u [threadIdx.x];
    }

    const int t = threadIdx.x;
    const int ntiles = E_N / EB;   // 3125 exact
    #pragma unroll 1
    for (int tile = blockIdx.x; tile < ntiles; tile += gridDim.x) {
        const int base = tile * EB;
        __syncthreads();
        #pragma unroll 1
        for (int i = t; i < EB * HDIM; i += NT)
            s_ef[(i / HDIM) * 51 + (i % HDIM)] = ef[(size_t)base * HDIM + i];
        #pragma unroll 1
        for (int i = t; i < EB; i += NT) { s_src[i] = srcp[base + i]; s_dst[i] = dstp[base + i]; }
        __syncthreads();

        const int e0 = t, e1 = t + NT;
        const float* f0 = s_ef + e0 * 51;
        const float* f1 = s_ef + e1 * 51;
        const int s0 = s_src[e0], s1 = s_src[e1];
        const int d0 = s_dst[e0], d1 = s_dst[e1];

        // phase 1: e2n message + scatter via red.v4
        {
            u64 t0[HP], t1[HP];
            const u64* B2 = reinterpret_cast<const u64*>(s_b2n);
            #pragma unroll
            for (int jj = 0; jj < HP; jj++) { t0[jj] = B2[jj]; t1[jj] = B2[jj]; }
            #pragma unroll 2
            for (int i = 0; i < HDIM; i++)
                accum_row<HP>(t0, t1, f0[i], f1[i], s_w2n + i * HDIM);

            float* A0 = g_acc + (size_t)d0 * PADW;
            float* A1 = g_acc + (size_t)d1 * PADW;
            #pragma unroll
            for (int c = 0; c < 12; c++) {
                float2 p = up2(t0[2 * c]), q = up2(t0[2 * c + 1]);
                red4(A0 + 4 * c, relu_f(p.x), relu_f(p.y), relu_f(q.x), relu_f(q.y));
            }
            { float2 p = up2(t0[24]); red2(A0 + 48, relu_f(p.x), relu_f(p.y)); }
            #pragma unroll
            for (int c = 0; c < 12; c++) {
                float2 p = up2(t1[2 * c]), q = up2(t1[2 * c + 1]);
                red4(A1 + 4 * c, relu_f(p.x), relu_f(p.y), relu_f(q.x), relu_f(q.y));
            }
            { float2 p = up2(t1[24]); red2(A1 + 48, relu_f(p.x), relu_f(p.y)); }
        }

        // phase 2: new_edge accumulator = bias
        u64 o0[HP], o1[HP];
        {
            const u64* B2 = reinterpret_cast<const u64*>(s_bu);
            #pragma unroll
            for (int jj = 0; jj < HP; jj++) { o0[jj] = B2[jj]; o1[jj] = B2[jj]; }
        }

        // third = relu(ef @ w_e2e + b) folded through w_u rows 100..149
        {   // cols [0,26)
            u64 t0[13], t1[13];
            const u64* B2 = reinterpret_cast<const u64*>(s_b2e);
            #pragma unroll
            for (int jj = 0; jj < 13; jj++) { t0[jj] = B2[jj]; t1[jj] = B2[jj]; }
            #pragma unroll 2
            for (int i = 0; i < HDIM; i++)
                accum_row<13>(t0, t1, f0[i], f1[i], s_w2e + i * HDIM);
            #pragma unroll
            for (int jj = 0; jj < 13; jj++) {
                float2 p0 = up2(t0[jj]), p1 = up2(t1[jj]);
                accum_row<HP>(o0, o1, relu_f(p0.x), relu_f(p1.x), s_wu + (100 + 2 * jj) * HDIM);
                accum_row<HP>(o0, o1, relu_f(p0.y), relu_f(p1.y), s_wu + (101 + 2 * jj) * HDIM);
            }
        }
        {   // cols [26,50)
            u64 t0[12], t1[12];
            const u64* B2 = reinterpret_cast<const u64*>(s_b2e + 26);
            #pragma unroll
            for (int jj = 0; jj < 12; jj++) { t0[jj] = B2[jj]; t1[jj] = B2[jj]; }
            #pragma unroll 2
            for (int i = 0; i < HDIM; i++)
                accum_row<12>(t0, t1, f0[i], f1[i], s_w2e + i * HDIM + 26);
            #pragma unroll
            for (int jj = 0; jj < 12; jj++) {
                float2 p0 = up2(t0[jj]), p1 = up2(t1[jj]);
                accum_row<HP>(o0, o1, relu_f(p0.x), relu_f(p1.x), s_wu + (126 + 2 * jj) * HDIM);
                accum_row<HP>(o0, o1, relu_f(p0.y), relu_f(p1.y), s_wu + (127 + 2 * jj) * HDIM);
            }
        }

        // first = relu(left[src]+right[dst]) @ w_u[0:50]
        gather_fold(o0, o1,
            reinterpret_cast<const float4*>(g_left  + (size_t)s0 * PADW),
            reinterpret_cast<const float4*>(g_right + (size_t)d0 * PADW),
            reinterpret_cast<const float4*>(g_left  + (size_t)s1 * PADW),
            reinterpret_cast<const float4*>(g_right + (size_t)d1 * PADW),
            s_wu);
        // second = relu(right[src]+left[dst]) @ w_u[50:100]
        gather_fold(o0, o1,
            reinterpret_cast<const float4*>(g_right + (size_t)s0 * PADW),
            reinterpret_cast<const float4*>(g_left  + (size_t)d0 * PADW),
            reinterpret_cast<const float4*>(g_right + (size_t)s1 * PADW),
            reinterpret_cast<const float4*>(g_left  + (size_t)d1 * PADW),
            s_wu + 50 * HDIM);

        float* O0 = out_edge + (size_t)(base + e0) * HDIM;
        float* O1 = out_edge + (size_t)(base + e1) * HDIM;
        #pragma unroll
        for (int jj = 0; jj < HP; jj++) {
            float2 p = up2(o0[jj]);
            reinterpret_cast<float2*>(O0)[jj] = make_float2(relu_f(p.x), relu_f(p.y));
            float2 q = up2(o1[jj]);
            reinterpret_cast<float2*>(O1)[jj] = make_float2(relu_f(q.x), relu_f(q.y));
        }
    }
}

// ---------------------------------------------------------------------------
// Kernel 3: new_node = relu([relu(nf@w_n2n+b) | g_acc] @ w_upd_n + b)
// ---------------------------------------------------------------------------
__global__ void __launch_bounds__(NT) k_node_final(
    const float* __restrict__ nf,
    const float* __restrict__ w_n2n, const float* __restrict__ b_n2n,
    const float* __restrict__ w_u,   const float* __restrict__ b_u,
    float* __restrict__ out_node)
{
    extern __shared__ float sm[];
    float* s_wn = sm;                    // 6400
    float* s_wu = sm + NI * HDIM;        // 5000 (100x50)
    float* s_bn = s_wu + 100 * HDIM;
    float* s_bu = s_bn + HDIM;
    for (int i = threadIdx.x; i < NI * HDIM; i += NT) s_wn[i] = w_n2n[i];
    for (int i = threadIdx.x; i < 100 * HDIM; i += NT) s_wu[i] = w_u[i];
    if (threadIdx.x < HDIM) { s_bn[threadIdx.x] = b_n2n[threadIdx.x]; s_bu[threadIdx.x] = b_u[threadIdx.x]; }
    __syncthreads();

    int v0 = (blockIdx.x * NT + threadIdx.x) * 2;
    if (v0 >= V_N) return;
    int v1 = v0 + 1;
    const float4* r0 = reinterpret_cast<const float4*>(nf + (size_t)v0 * NI);
    const float4* r1 = reinterpret_cast<const float4*>(nf + (size_t)v1 * NI);

    u64 o0[HP], o1[HP];
    {
        const u64* B2 = reinterpret_cast<const u64*>(s_bu);
        #pragma unroll
        for (int jj = 0; jj < HP; jj++) { o0[jj] = B2[jj]; o1[jj] = B2[jj]; }
    }
    // node_node cols [0,26) then [26,50), folded through w_u rows 0..49
    {
        u64 t0[13], t1[13];
        const u64* B2 = reinterpret_cast<const u64*>(s_bn);
        #pragma unroll
        for (int jj = 0; jj < 13; jj++) { t0[jj] = B2[jj]; t1[jj] = B2[jj]; }
        #pragma unroll 1
        for (int c = 0; c < NI / 4; c++) {
            float4 x0 = __ldg(r0 + c), x1 = __ldg(r1 + c);
            accum_row<13>(t0, t1, x0.x, x1.x, s_wn + (4 * c + 0) * HDIM);
            accum_row<13>(t0, t1, x0.y, x1.y, s_wn + (4 * c + 1) * HDIM);
            accum_row<13>(t0, t1, x0.z, x1.z, s_wn + (4 * c + 2) * HDIM);
            accum_row<13>(t0, t1, x0.w, x1.w, s_wn + (4 * c + 3) * HDIM);
        }
        #pragma unroll
        for (int jj = 0; jj < 13; jj++) {
            float2 p0 = up2(t0[jj]), p1 = up2(t1[jj]);
            accum_row<HP>(o0, o1, relu_f(p0.x), relu_f(p1.x), s_wu + (2 * jj) * HDIM);
            accum_row<HP>(o0, o1, relu_f(p0.y), relu_f(p1.y), s_wu + (2 * jj + 1) * HDIM);
        }
    }
    {
        u64 t0[12], t1[12];
        const u64* B2 = reinterpret_cast<const u64*>(s_bn + 26);
        #pragma unroll
        for (int jj = 0; jj < 12; jj++) { t0[jj] = B2[jj]; t1[jj] = B2[jj]; }
        #pragma unroll 1
        for (int c = 0; c < NI / 4; c++) {
            float4 x0 = __ldg(r0 + c), x1 = __ldg(r1 + c);
            accum_row<12>(t0, t1, x0.x, x1.x, s_wn + (4 * c + 0) * HDIM + 26);
            accum_row<12>(t0, t1, x0.y, x1.y, s_wn + (4 * c + 1) * HDIM + 26);
            accum_row<12>(t0, t1, x0.z, x1.z, s_wn + (4 * c + 2) * HDIM + 26);
            accum_row<12>(t0, t1, x0.w, x1.w, s_wn + (4 * c + 3) * HDIM + 26);
        }
        #pragma unroll
        for (int jj = 0; jj < 12; jj++) {
            float2 p0 = up2(t0[jj]), p1 = up2(t1[jj]);
            accum_row<HP>(o0, o1, relu_f(p0.x), relu_f(p1.x), s_wu + (26 + 2 * jj) * HDIM);
            accum_row<HP>(o0, o1, relu_f(p0.y), relu_f(p1.y), s_wu + (27 + 2 * jj) * HDIM);
        }
    }
    // edge_node (raw sums) folded through w_u rows 50..99
    {
        const float4* A0 = reinterpret_cast<const float4*>(g_acc + (size_t)v0 * PADW);
        const float4* A1 = reinterpret_cast<const float4*>(g_acc + (size_t)v1 * PADW);
        #pragma unroll 1
        for (int c = 0; c < 12; c++) {
            float4 a0 = A0[c], a1 = A1[c];
            const float* W = s_wu + (50 + 4 * c) * HDIM;
            accum_row<HP>(o0, o1, a0.x, a1.x, W);
            accum_row<HP>(o0, o1, a0.y, a1.y, W + HDIM);
            accum_row<HP>(o0, o1, a0.z, a1.z, W + 2 * HDIM);
            accum_row<HP>(o0, o1, a0.w, a1.w, W + 3 * HDIM);
        }
        float4 a0 = A0[12], a1 = A1[12];
        const float* W = s_wu + 98 * HDIM;
        accum_row<HP>(o0, o1, a0.x, a1.x, W);
        accum_row<HP>(o0, o1, a0.y, a1.y, W + HDIM);
    }

    float* O0 = out_node + (size_t)v0 * HDIM;
    float* O1 = out_node + (size_t)v1 * HDIM;
    #pragma unroll
    for (int jj = 0; jj < HP; jj++) {
        float2 p = up2(o0[jj]);
        reinterpret_cast<float2*>(O0)[jj] = make_float2(relu_f(p.x), relu_f(p.y));
        float2 q = up2(o1[jj]);
        reinterpret_cast<float2*>(O1)[jj] = make_float2(relu_f(q.x), relu_f(q.y));
    }
}

// ---------------------------------------------------------------------------
extern "C" void kernel_launch(void* const* d_in, const int* in_sizes, int n_in,
                              void* d_out, int out_size) {
    const float* nf    = (const float*)d_in[0];
    const float* ef    = (const float*)d_in[1];
    const int*   srcp  = (const int*)d_in[2];
    const int*   dstp  = (const int*)d_in[3];
    const float* w_n2n = (const float*)d_in[4];  const float* b_n2n = (const float*)d_in[5];
    const float* w_e2n = (const float*)d_in[6];  const float* b_e2n = (const float*)d_in[7];
    const float* w_upn = (const float*)d_in[8];  const float* b_upn = (const float*)d_in[9];
    const float* w_l   = (const float*)d_in[10]; const float* b_l   = (const float*)d_in[11];
    const float* w_r   = (const float*)d_in[12]; const float* b_r   = (const float*)d_in[13];
    const float* w_e2e = (const float*)d_in[14]; const float* b_e2e = (const float*)d_in[15];
    const float* w_upe = (const float*)d_in[16]; const float* b_upe = (const float*)d_in[17];

    float* out_node = (float*)d_out;
    float* out_edge = out_node + (size_t)V_N * HDIM;

    size_t sm_lr   = (size_t)(2 * NI * HDIM + 2 * HDIM) * 4;
    size_t sm_edge = (size_t)(EB * 51 + 2500 + 2500 + 7500 + 3 * HDIM) * 4 + EB * 2 * 4;
    size_t sm_fin  = (size_t)(NI * HDIM + 100 * HDIM + 2 * HDIM) * 4;

    cudaFuncSetAttribute(k_node_lr,    cudaFuncAttributeMaxDynamicSharedMemorySize, (int)sm_lr);
    cudaFuncSetAttribute(k_edge,       cudaFuncAttributeMaxDynamicSharedMemorySize, (int)sm_edge);
    cudaFuncSetAttribute(k_node_final, cudaFuncAttributeMaxDynamicSharedMemorySize, (int)sm_fin);

    int nblk = (V_N / 2 + NT - 1) / NT;   // 196
    k_node_lr<<<nblk, NT, sm_lr>>>(nf, w_l, b_l, w_r, b_r);
    k_edge<<<148, NT, sm_edge>>>(ef, srcp, dstp, w_e2n, b_e2n, w_e2e, b_e2e,
                                 w_upe, b_upe, out_edge);
    k_node_final<<<nblk, NT, sm_fin>>>(nf, w_n2n, b_n2n, w_upn, b_upn, out_node);
}

// round 3
// speedup vs baseline: 1.5319x; 1.5319x over previous
#include <cuda_runtime.h>

#define V_N   100000
#define E_N   1600000
#define NI    128
#define H     50
#define PW    52          // padded row width (13 float4)
#define EFW   53          // edge-feature smem stride (odd -> bank-conflict-free)
#define EB    512         // edges per tile
#define NTE   512         // k_edge threads
#define NT    256         // node kernel threads

typedef unsigned long long u64;

__device__ float g_left [(size_t)V_N * PW];
__device__ float g_right[(size_t)V_N * PW];
__device__ float g_acc  [(size_t)V_N * PW];

// ---- helpers --------------------------------------------------------------
__device__ __forceinline__ u64 pk2(float x, float y) {
    u64 r; asm("mov.b64 %0, {%1, %2};" : "=l"(r) : "f"(x), "f"(y)); return r;
}
__device__ __forceinline__ float2 up2(u64 v) {
    float2 r; asm("mov.b64 {%0, %1}, %2;" : "=f"(r.x), "=f"(r.y) : "l"(v)); return r;
}
__device__ __forceinline__ u64 ffma2(u64 a, u64 b, u64 c) {
    u64 d; asm("fma.rn.f32x2 %0, %1, %2, %3;" : "=l"(d) : "l"(a), "l"(b), "l"(c)); return d;
}
__device__ __forceinline__ float relu_f(float x) { return fmaxf(x, 0.0f); }

__device__ __forceinline__ void red4(float* p, float a, float b, float c, float d) {
    asm volatile("red.global.add.v4.f32 [%0], {%1,%2,%3,%4};"
                 :: "l"(p), "f"(a), "f"(b), "f"(c), "f"(d) : "memory");
}

// a[0..2Q) u64 accum pairs += x * Wrow[0..4Q)   (Wrow 16B-aligned, LDS.128)
template <int Q>
__device__ __forceinline__ void acc1(u64* a, float x, const float* Wrow) {
    u64 xx = pk2(x, x);
    const ulonglong2* w = reinterpret_cast<const ulonglong2*>(Wrow);
    #pragma unroll
    for (int q = 0; q < Q; q++) {
        ulonglong2 ww = w[q];
        a[2 * q]     = ffma2(xx, ww.x, a[2 * q]);
        a[2 * q + 1] = ffma2(xx, ww.y, a[2 * q + 1]);
    }
}

// stage [rows_real x 50] fp32 matrix into padded [rows_pad x 52] smem, zero pads
__device__ __forceinline__ void stage_w(float* s, const float* g, int rows_real,
                                        int rows_pad, int tid, int nt) {
    int tot = rows_pad * PW;
    for (int i = tid; i < tot; i += nt) {
        int r = i / PW, c = i % PW;
        s[i] = (c < H && r < rows_real) ? g[r * H + c] : 0.0f;
    }
}
__device__ __forceinline__ void stage_b(float* s, const float* g, int tid) {
    if (tid < PW) s[tid] = (tid < H) ? g[tid] : 0.0f;
}

// ---------------------------------------------------------------------------
// Kernel 1: left/right tables (no relu) + zero scatter accumulator
// ---------------------------------------------------------------------------
__global__ void __launch_bounds__(NT) k_node_lr(
    const float* __restrict__ nf,
    const float* __restrict__ w_l, const float* __restrict__ b_l,
    const float* __restrict__ w_r, const float* __restrict__ b_r)
{
    extern __shared__ float sm[];
    float* s_wl = sm;                 // 128*52
    float* s_wr = s_wl + NI * PW;     // 128*52
    float* s_bl = s_wr + NI * PW;     // 52
    float* s_br = s_bl + PW;          // 52
    stage_w(s_wl, w_l, NI, NI, threadIdx.x, NT);
    stage_w(s_wr, w_r, NI, NI, threadIdx.x, NT);
    stage_b(s_bl, b_l, threadIdx.x);
    stage_b(s_br, b_r, threadIdx.x);

    {   // zero g_acc
        float4 z = make_float4(0.f, 0.f, 0.f, 0.f);
        size_t tot = (size_t)V_N * PW / 4;
        for (size_t i = (size_t)blockIdx.x * NT + threadIdx.x; i < tot; i += (size_t)gridDim.x * NT)
            reinterpret_cast<float4*>(g_acc)[i] = z;
    }
    __syncthreads();

    int v = blockIdx.x * NT + threadIdx.x;
    if (v >= V_N) return;
    const float4* r0 = reinterpret_cast<const float4*>(nf + (size_t)v * NI);

    #pragma unroll 1
    for (int pass = 0; pass < 2; pass++) {
        const float* W = pass ? s_wr : s_wl;
        const u64*  B2 = reinterpret_cast<const u64*>(pass ? s_br : s_bl);
        u64 a[26];
        #pragma unroll
        for (int q = 0; q < 26; q++) a[q] = B2[q];
        #pragma unroll 1
        for (int c = 0; c < NI / 4; c++) {
            float4 x = __ldg(r0 + c);
            acc1<13>(a, x.x, W + (4 * c + 0) * PW);
            acc1<13>(a, x.y, W + (4 * c + 1) * PW);
            acc1<13>(a, x.z, W + (4 * c + 2) * PW);
            acc1<13>(a, x.w, W + (4 * c + 3) * PW);
        }
        float* dp = (pass ? g_right : g_left) + (size_t)v * PW;
        #pragma unroll
        for (int q = 0; q < 13; q++) {
            ulonglong2 uu; uu.x = a[2 * q]; uu.y = a[2 * q + 1];
            reinterpret_cast<ulonglong2*>(dp)[q] = uu;   // pads store bias-pad = 0
        }
    }
}

// ---------------------------------------------------------------------------
// Kernel 2: edge pass (persistent, 1 edge/thread, 512 threads)
// ---------------------------------------------------------------------------
__global__ void __launch_bounds__(NTE) k_edge(
    const float* __restrict__ ef, const int* __restrict__ srcp, const int* __restrict__ dstp,
    const float* __restrict__ w_e2n, const float* __restrict__ b_e2n,
    const float* __restrict__ w_e2e, const float* __restrict__ b_e2e,
    const float* __restrict__ w_u,  const float* __restrict__ b_u,
    float* __restrict__ out_edge)
{
    extern __shared__ float sm[];
    float* s_ef  = sm;                   // EB*53
    float* s_w2n = s_ef + EB * EFW;      // 50*52
    float* s_w2e = s_w2n + H * PW;       // 50*52
    float* s_wu  = s_w2e + H * PW;       // 152*52
    float* s_b2n = s_wu + 152 * PW;      // 52
    float* s_b2e = s_b2n + PW;           // 52
    float* s_bu  = s_b2e + PW;           // 52
    int*   s_src = reinterpret_cast<int*>(s_bu + PW);   // EB
    int*   s_dst = s_src + EB;                          // EB

    const int t = threadIdx.x;
    stage_w(s_w2n, w_e2n, H, H, t, NTE);
    stage_w(s_w2e, w_e2e, H, H, t, NTE);
    stage_w(s_wu,  w_u, 150, 152, t, NTE);
    stage_b(s_b2n, b_e2n, t);
    stage_b(s_b2e, b_e2e, t);
    stage_b(s_bu,  b_u,  t);

    const int ntiles = E_N / EB;   // 3125 exact
    #pragma unroll 1
    for (int tile = blockIdx.x; tile < ntiles; tile += gridDim.x) {
        const int base = tile * EB;
        __syncthreads();                       // prev tile consumed / weights ready
        #pragma unroll 1
        for (int i = t; i < EB * H; i += NTE)
            s_ef[(i / H) * EFW + (i % H)] = ef[(size_t)base * H + i];
        if (t < EB) { s_src[t] = srcp[base + t]; s_dst[t] = dstp[base + t]; }
        __syncthreads();

        const float* f = s_ef + t * EFW;
        const int s0 = s_src[t], d0 = s_dst[t];

        // ---- phase 1: e2n message -> relu -> red.v4 scatter onto g_acc[dst]
        {
            u64 a[26];
            const u64* B2 = reinterpret_cast<const u64*>(s_b2n);
            #pragma unroll
            for (int q = 0; q < 26; q++) a[q] = B2[q];
            #pragma unroll 2
            for (int i = 0; i < H; i++)
                acc1<13>(a, f[i], s_w2n + i * PW);
            float* A = g_acc + (size_t)d0 * PW;
            #pragma unroll
            for (int c = 0; c < 13; c++) {
                float2 p = up2(a[2 * c]), q2 = up2(a[2 * c + 1]);
                red4(A + 4 * c, relu_f(p.x), relu_f(p.y), relu_f(q2.x), relu_f(q2.y));
            }
        }

        // ---- phase 2: new_edge
        u64 o[26];
        {
            const u64* B2 = reinterpret_cast<const u64*>(s_bu);
            #pragma unroll
            for (int q = 0; q < 26; q++) o[q] = B2[q];
        }

        // third = relu(ef @ w_e2e + b), folded through w_u rows 100..151
        {   // cols [0,28)
            u64 tA[14];
            const u64* B2 = reinterpret_cast<const u64*>(s_b2e);
            #pragma unroll
            for (int q = 0; q < 14; q++) tA[q] = B2[q];
            #pragma unroll 2
            for (int i = 0; i < H; i++)
                acc1<7>(tA, f[i], s_w2e + i * PW);
            #pragma unroll
            for (int k = 0; k < 14; k++) {
                float2 p = up2(tA[k]);
                acc1<13>(o, relu_f(p.x), s_wu + (100 + 2 * k) * PW);
                acc1<13>(o, relu_f(p.y), s_wu + (101 + 2 * k) * PW);
            }
        }
        {   // cols [28,52): pads produce relu(0)=0 and hit zeroed w_u rows 150,151
            u64 tB[12];
            const u64* B2 = reinterpret_cast<const u64*>(s_b2e + 28);
            #pragma unroll
            for (int q = 0; q < 12; q++) tB[q] = B2[q];
            #pragma unroll 2
            for (int i = 0; i < H; i++)
                acc1<6>(tB, f[i], s_w2e + i * PW + 28);
            #pragma unroll
            for (int k = 0; k < 12; k++) {
                float2 p = up2(tB[k]);
                acc1<13>(o, relu_f(p.x), s_wu + (128 + 2 * k) * PW);
                acc1<13>(o, relu_f(p.y), s_wu + (129 + 2 * k) * PW);
            }
        }

        // first = relu(left[src]+right[dst]) @ w_u rows 0..49 (pads x=0)
        {
            const float4* La = reinterpret_cast<const float4*>(g_left  + (size_t)s0 * PW);
            const float4* Rb = reinterpret_cast<const float4*>(g_right + (size_t)d0 * PW);
            #pragma unroll 1
            for (int c = 0; c < 13; c++) {
                float4 a = __ldg(La + c), b = __ldg(Rb + c);
                acc1<13>(o, relu_f(a.x + b.x), s_wu + (4 * c + 0) * PW);
                acc1<13>(o, relu_f(a.y + b.y), s_wu + (4 * c + 1) * PW);
                acc1<13>(o, relu_f(a.z + b.z), s_wu + (4 * c + 2) * PW);
                acc1<13>(o, relu_f(a.w + b.w), s_wu + (4 * c + 3) * PW);
            }
        }
        // second = relu(right[src]+left[dst]) @ w_u rows 50..99 (pads x=0)
        {
            const float4* Ra = reinterpret_cast<const float4*>(g_right + (size_t)s0 * PW);
            const float4* Lb = reinterpret_cast<const float4*>(g_left  + (size_t)d0 * PW);
            #pragma unroll 1
            for (int c = 0; c < 13; c++) {
                float4 a = __ldg(Ra + c), b = __ldg(Lb + c);
                acc1<13>(o, relu_f(a.x + b.x), s_wu + (50 + 4 * c + 0) * PW);
                acc1<13>(o, relu_f(a.y + b.y), s_wu + (50 + 4 * c + 1) * PW);
                acc1<13>(o, relu_f(a.z + b.z), s_wu + (50 + 4 * c + 2) * PW);
                acc1<13>(o, relu_f(a.w + b.w), s_wu + (50 + 4 * c + 3) * PW);
            }
        }

        float* O = out_edge + (size_t)(base + t) * H;
        #pragma unroll
        for (int q = 0; q < 25; q++) {
            float2 p = up2(o[q]);
            reinterpret_cast<float2*>(O)[q] = make_float2(relu_f(p.x), relu_f(p.y));
        }
    }
}

// ---------------------------------------------------------------------------
// Kernel 3: new_node = relu([relu(nf@w_n2n+b) | g_acc] @ w_upd_n + b)
// ---------------------------------------------------------------------------
__global__ void __launch_bounds__(NT) k_node_final(
    const float* __restrict__ nf,
    const float* __restrict__ w_n2n, const float* __restrict__ b_n2n,
    const float* __restrict__ w_u,   const float* __restrict__ b_u,
    float* __restrict__ out_node)
{
    extern __shared__ float sm[];
    float* s_wn = sm;                   // 128*52
    float* s_wu = s_wn + NI * PW;       // 102*52
    float* s_bn = s_wu + 102 * PW;      // 52
    float* s_bu = s_bn + PW;            // 52
    stage_w(s_wn, w_n2n, NI, NI, threadIdx.x, NT);
    stage_w(s_wu, w_u, 100, 102, threadIdx.x, NT);
    stage_b(s_bn, b_n2n, threadIdx.x);
    stage_b(s_bu, b_u, threadIdx.x);
    __syncthreads();

    int v = blockIdx.x * NT + threadIdx.x;
    if (v >= V_N) return;
    const float4* r0 = reinterpret_cast<const float4*>(nf + (size_t)v * NI);

    u64 o[26];
    {
        const u64* B2 = reinterpret_cast<const u64*>(s_bu);
        #pragma unroll
        for (int q = 0; q < 26; q++) o[q] = B2[q];
    }

    // node_node cols [0,28) then [28,52), folded through w_u rows 0..51
    {
        u64 tA[14];
        const u64* B2 = reinterpret_cast<const u64*>(s_bn);
        #pragma unroll
        for (int q = 0; q < 14; q++) tA[q] = B2[q];
        #pragma unroll 1
        for (int c = 0; c < NI / 4; c++) {
            float4 x = __ldg(r0 + c);
            acc1<7>(tA, x.x, s_wn + (4 * c + 0) * PW);
            acc1<7>(tA, x.y, s_wn + (4 * c + 1) * PW);
            acc1<7>(tA, x.z, s_wn + (4 * c + 2) * PW);
            acc1<7>(tA, x.w, s_wn + (4 * c + 3) * PW);
        }
        #pragma unroll
        for (int k = 0; k < 14; k++) {
            float2 p = up2(tA[k]);
            acc1<13>(o, relu_f(p.x), s_wu + (2 * k) * PW);
            acc1<13>(o, relu_f(p.y), s_wu + (2 * k + 1) * PW);
        }
    }
    {
        u64 tB[12];
        const u64* B2 = reinterpret_cast<const u64*>(s_bn + 28);
        #pragma unroll
        for (int q = 0; q < 12; q++) tB[q] = B2[q];
        #pragma unroll 1
        for (int c = 0; c < NI / 4; c++) {
            float4 x = __ldg(r0 + c);
            acc1<6>(tB, x.x, s_wn + (4 * c + 0) * PW + 28);
            acc1<6>(tB, x.y, s_wn + (4 * c + 1) * PW + 28);
            acc1<6>(tB, x.z, s_wn + (4 * c + 2) * PW + 28);
            acc1<6>(tB, x.w, s_wn + (4 * c + 3) * PW + 28);
        }
        #pragma unroll
        for (int k = 0; k < 12; k++) {
            float2 p = up2(tB[k]);
            acc1<13>(o, relu_f(p.x), s_wu + (28 + 2 * k) * PW);
            acc1<13>(o, relu_f(p.y), s_wu + (29 + 2 * k) * PW);
        }
    }
    // edge_node (raw sums incl 0-pads) through w_u rows 50..101 (100,101 zeroed)
    {
        const float4* A = reinterpret_cast<const float4*>(g_acc + (size_t)v * PW);
        #pragma unroll 1
        for (int c = 0; c < 13; c++) {
            float4 a = __ldg(A + c);
            acc1<13>(o, a.x, s_wu + (50 + 4 * c + 0) * PW);
            acc1<13>(o, a.y, s_wu + (50 + 4 * c + 1) * PW);
            acc1<13>(o, a.z, s_wu + (50 + 4 * c + 2) * PW);
            acc1<13>(o, a.w, s_wu + (50 + 4 * c + 3) * PW);
        }
    }

    float* O = out_node + (size_t)v * H;
    #pragma unroll
    for (int q = 0; q < 25; q++) {
        float2 p = up2(o[q]);
        reinterpret_cast<float2*>(O)[q] = make_float2(relu_f(p.x), relu_f(p.y));
    }
}

// ---------------------------------------------------------------------------
extern "C" void kernel_launch(void* const* d_in, const int* in_sizes, int n_in,
                              void* d_out, int out_size) {
    const float* nf    = (const float*)d_in[0];
    const float* ef    = (const float*)d_in[1];
    const int*   srcp  = (const int*)d_in[2];
    const int*   dstp  = (const int*)d_in[3];
    const float* w_n2n = (const float*)d_in[4];  const float* b_n2n = (const float*)d_in[5];
    const float* w_e2n = (const float*)d_in[6];  const float* b_e2n = (const float*)d_in[7];
    const float* w_upn = (const float*)d_in[8];  const float* b_upn = (const float*)d_in[9];
    const float* w_l   = (const float*)d_in[10]; const float* b_l   = (const float*)d_in[11];
    const float* w_r   = (const float*)d_in[12]; const float* b_r   = (const float*)d_in[13];
    const float* w_e2e = (const float*)d_in[14]; const float* b_e2e = (const float*)d_in[15];
    const float* w_upe = (const float*)d_in[16]; const float* b_upe = (const float*)d_in[17];

    float* out_node = (float*)d_out;
    float* out_edge = out_node + (size_t)V_N * H;

    size_t sm_lr   = (size_t)(2 * NI * PW + 2 * PW) * 4;
    size_t sm_edge = (size_t)(EB * EFW + 2 * H * PW + 152 * PW + 3 * PW) * 4 + 2 * EB * 4;
    size_t sm_fin  = (size_t)(NI * PW + 102 * PW + 2 * PW) * 4;

    cudaFuncSetAttribute(k_node_lr,    cudaFuncAttributeMaxDynamicSharedMemorySize, (int)sm_lr);
    cudaFuncSetAttribute(k_edge,       cudaFuncAttributeMaxDynamicSharedMemorySize, (int)sm_edge);
    cudaFuncSetAttribute(k_node_final, cudaFuncAttributeMaxDynamicSharedMemorySize, (int)sm_fin);

    int nblk = (V_N + NT - 1) / NT;   // 391
    k_node_lr<<<nblk, NT, sm_lr>>>(nf, w_l, b_l, w_r, b_r);
    k_edge<<<148, NTE, sm_edge>>>(ef, srcp, dstp, w_e2n, b_e2n, w_e2e, b_e2e,
                                  w_upe, b_upe, out_edge);
    k_node_final<<<nblk, NT, sm_fin>>>(nf, w_n2n, b_n2n, w_upn, b_upn, out_node);
}